// round 3
// baseline (speedup 1.0000x reference)
#include <cuda_runtime.h>
#include <stdint.h>

// Problem constants
#define NT    256      // threads per CTA (4 b-groups x 64 channels)
#define NBSUB 4        // b-values per thread
#define NB    16       // b-values per CTA (4 groups * 4 sub)
#define DIM   40
#define NPAIR 820      // DIM*(DIM+1)/2 unique symmetric pairs
#define NROWS 860      // pairs + 40 U1 rows
#define TS    16       // table row stride (floats)
#define XROWB 4096     // x_s row stride in bytes (256 float4 per i-row)

// Packed coefficient table (global; read via LDG broadcast, L1-resident):
//  rows [0,820): per pair (i<=j): 13 symmetric-folded U2 coeffs (off-diag doubled),
//                pad(0), then bit-cast byte offsets i*4096, j*4096
//  rows [820,860): per i: 13 U1 coeffs, pad, offset i*4096, 0
__device__ float g_table[NROWS * TS];

__global__ void prep_kernel(const float* __restrict__ U2_0,
                            const float* __restrict__ U1_0,
                            const float* __restrict__ U2_1,
                            const float* __restrict__ U1_1,
                            const float* __restrict__ U2_2,
                            const float* __restrict__ U1_2) {
    int idx = blockIdx.x * blockDim.x + threadIdx.x;
    if (idx >= NROWS) return;
    float row[TS];
#pragma unroll
    for (int k = 0; k < TS; k++) row[k] = 0.0f;

    if (idx < NPAIR) {
        int p = idx;
        int j = 0;
        while ((j + 1) * (j + 2) / 2 <= p) j++;
        int i = p - j * (j + 1) / 2;   // i <= j
        const float* U2b[3] = {U2_0, U2_1, U2_2};
#pragma unroll
        for (int m = 0; m < 13; m++) {
            int l  = (m == 0) ? 0 : ((m < 4) ? 1 : 2);
            int mm = (m == 0) ? 0 : ((m < 4) ? (m - 1) : (m - 4));
            const float* U = U2b[l];
            float v = U[(mm * DIM + i) * DIM + j];
            if (i != j) v += U[(mm * DIM + j) * DIM + i];
            row[m] = v;
        }
        row[13] = 0.0f;
        row[14] = __int_as_float(i * XROWB);
        row[15] = __int_as_float(j * XROWB);
    } else {
        int i = idx - NPAIR;
        const float* U1b[3] = {U1_0, U1_1, U1_2};
#pragma unroll
        for (int m = 0; m < 13; m++) {
            int l  = (m == 0) ? 0 : ((m < 4) ? 1 : 2);
            int mm = (m == 0) ? 0 : ((m < 4) ? (m - 1) : (m - 4));
            row[m] = U1b[l][mm * DIM + i];
        }
        row[13] = 0.0f;
        row[14] = __int_as_float(i * XROWB);
        row[15] = __int_as_float(0);
    }
#pragma unroll
    for (int k = 0; k < TS; k++) g_table[idx * TS + k] = row[k];
}

// ---- packed f32x2 helpers (FFMA2 is only reachable via PTX) ----
__device__ __forceinline__ void fma2(unsigned long long& acc,
                                     unsigned long long u,
                                     unsigned long long y) {
    asm("fma.rn.f32x2 %0, %1, %2, %0;" : "+l"(acc) : "l"(u), "l"(y));
}
__device__ __forceinline__ unsigned long long dup2(float y) {
    unsigned long long r;
    asm("mov.b64 %0, {%1, %1};" : "=l"(r) : "f"(y));
    return r;
}
__device__ __forceinline__ float2 unpk2(unsigned long long v) {
    float2 r;
    asm("mov.b64 {%0, %1}, %2;" : "=f"(r.x), "=f"(r.y) : "l"(v));
    return r;
}

// SMEM layout (floats):
//   [0,     40960)  xS: x[40][4 groups][64 c][4 b-sub]  (160 KB, float4-packed)
//                   first 12288 floats reused for Wlin after phase B
//   [40960, 57344)  basis[16 b][64 c][16 m]             (64 KB)
#define SMEM_FLOATS 57344
#define SMEM_BYTES  (SMEM_FLOATS * 4)

__global__ __launch_bounds__(NT, 1)
void main_kernel(const float* __restrict__ f0,  const float* __restrict__ f1,
                 const float* __restrict__ f2,  const float* __restrict__ f3,
                 const float* __restrict__ attrs,
                 const float* __restrict__ W1_0, const float* __restrict__ W2_0,
                 const float* __restrict__ Wl0,  const float* __restrict__ sc0,
                 const float* __restrict__ W1_1, const float* __restrict__ W2_1,
                 const float* __restrict__ Wl1,  const float* __restrict__ sc1,
                 const float* __restrict__ W1_2, const float* __restrict__ W2_2,
                 const float* __restrict__ Wl2,  const float* __restrict__ sc2,
                 float* __restrict__ out, int B) {
    extern __shared__ float S[];
    float* xS   = S;            // 40960 floats
    float* basS = S + 40960;    // 16384 floats

    const int tid = threadIdx.x;
    const int g   = tid >> 6;        // b-group 0..3
    const int c   = tid & 63;        // channel
    const int bg  = blockIdx.x * NB + g * NBSUB;  // first b of this thread

    // ---- gather x for 4 b's into float4-packed smem: xS4[i*256 + g*64 + c] ----
    {
        const int lane4 = (g * 64 + c) * 4;   // float index within an i-row
#pragma unroll
        for (int s = 0; s < NBSUB; s++) {
            int bb = bg + s; if (bb >= B) bb = B - 1;
            const int base = bb * 64 + c;
            xS[(0 * 256) * 4 + lane4 + s] = f0[base];
#pragma unroll
            for (int k = 0; k < 3; k++)
                xS[((1 + k) * 256) * 4 + lane4 + s]  = f1[base * 3 + k];
#pragma unroll
            for (int k = 0; k < 9; k++)
                xS[((4 + k) * 256) * 4 + lane4 + s]  = f2[base * 9 + k];
#pragma unroll
            for (int k = 0; k < 27; k++)
                xS[((13 + k) * 256) * 4 + lane4 + s] = f3[base * 27 + k];
        }
    }
    __syncthreads();

    const char* xb = (const char*)xS + (g * 64 + c) * 16;

    // ---- phase A: a2[s][m] = sum_pairs u[p][m] * x_i[s] * x_j[s] ----
    unsigned long long acc[NBSUB][7];
#pragma unroll
    for (int s = 0; s < NBSUB; s++)
#pragma unroll
        for (int k = 0; k < 7; k++) acc[s][k] = 0ull;

    const ulonglong2* trow = (const ulonglong2*)g_table;
#pragma unroll 2
    for (int p = 0; p < NPAIR; p++, trow += 4) {
        ulonglong2 q0 = __ldg(trow);
        ulonglong2 q1 = __ldg(trow + 1);
        ulonglong2 q2 = __ldg(trow + 2);
        ulonglong2 q3 = __ldg(trow + 3);
        unsigned int io = (unsigned int)(q3.y);
        unsigned int jo = (unsigned int)(q3.y >> 32);
        float4 xi = *(const float4*)(xb + io);
        float4 xj = *(const float4*)(xb + jo);
        unsigned long long y0 = dup2(xi.x * xj.x);
        unsigned long long y1 = dup2(xi.y * xj.y);
        unsigned long long y2 = dup2(xi.z * xj.z);
        unsigned long long y3 = dup2(xi.w * xj.w);
        fma2(acc[0][0], q0.x, y0); fma2(acc[1][0], q0.x, y1);
        fma2(acc[2][0], q0.x, y2); fma2(acc[3][0], q0.x, y3);
        fma2(acc[0][1], q0.y, y0); fma2(acc[1][1], q0.y, y1);
        fma2(acc[2][1], q0.y, y2); fma2(acc[3][1], q0.y, y3);
        fma2(acc[0][2], q1.x, y0); fma2(acc[1][2], q1.x, y1);
        fma2(acc[2][2], q1.x, y2); fma2(acc[3][2], q1.x, y3);
        fma2(acc[0][3], q1.y, y0); fma2(acc[1][3], q1.y, y1);
        fma2(acc[2][3], q1.y, y2); fma2(acc[3][3], q1.y, y3);
        fma2(acc[0][4], q2.x, y0); fma2(acc[1][4], q2.x, y1);
        fma2(acc[2][4], q2.x, y2); fma2(acc[3][4], q2.x, y3);
        fma2(acc[0][5], q2.y, y0); fma2(acc[1][5], q2.y, y1);
        fma2(acc[2][5], q2.y, y2); fma2(acc[3][5], q2.y, y3);
        fma2(acc[0][6], q3.x, y0); fma2(acc[1][6], q3.x, y1);
        fma2(acc[2][6], q3.x, y2); fma2(acc[3][6], q3.x, y3);
    }

    // ---- element-aware channel weights for 4 b's ----
    float w1v[NBSUB][3], w2v[NBSUB][3];
#pragma unroll
    for (int s = 0; s < NBSUB; s++) {
        int bb = bg + s; if (bb >= B) bb = B - 1;
        float a1w0 = 0.f, a1w1 = 0.f, a1w2 = 0.f;
        float a2w0 = 0.f, a2w1 = 0.f, a2w2 = 0.f;
#pragma unroll
        for (int e = 0; e < 10; e++) {
            float a = __ldg(&attrs[bb * 10 + e]);
            a1w0 += a * __ldg(&W1_0[e * 64 + c]);
            a2w0 += a * __ldg(&W2_0[e * 64 + c]);
            a1w1 += a * __ldg(&W1_1[e * 64 + c]);
            a2w1 += a * __ldg(&W2_1[e * 64 + c]);
            a1w2 += a * __ldg(&W1_2[e * 64 + c]);
            a2w2 += a * __ldg(&W2_2[e * 64 + c]);
        }
        w1v[s][0] = a1w0; w1v[s][1] = a1w1; w1v[s][2] = a1w2;
        w2v[s][0] = a2w0; w2v[s][1] = a2w1; w2v[s][2] = a2w2;
    }

    const int LSEL[14] = {0, 1, 1, 1, 2, 2, 2, 2, 2, 2, 2, 2, 2, 0};

    // fold a2 * w2 into basis smem
#pragma unroll
    for (int s = 0; s < NBSUB; s++) {
        float* bs = basS + ((g * NBSUB + s) * 64 + c) * 16;
#pragma unroll
        for (int k = 0; k < 7; k++) {
            float2 v = unpk2(acc[s][k]);
            int m0 = 2 * k, m1 = 2 * k + 1;
            bs[m0] = v.x * w2v[s][LSEL[m0]];
            if (m1 < 13) bs[m1] = v.y * w2v[s][LSEL[m1]];
        }
    }

    // ---- phase B: a1[s][m] = U1[m,:] . x[s]  (reuse acc regs) ----
#pragma unroll
    for (int s = 0; s < NBSUB; s++)
#pragma unroll
        for (int k = 0; k < 7; k++) acc[s][k] = 0ull;

#pragma unroll 2
    for (int r = 0; r < DIM; r++, trow += 4) {
        ulonglong2 q0 = __ldg(trow);
        ulonglong2 q1 = __ldg(trow + 1);
        ulonglong2 q2 = __ldg(trow + 2);
        ulonglong2 q3 = __ldg(trow + 3);
        unsigned int io = (unsigned int)(q3.y);
        float4 xi = *(const float4*)(xb + io);
        unsigned long long y0 = dup2(xi.x);
        unsigned long long y1 = dup2(xi.y);
        unsigned long long y2 = dup2(xi.z);
        unsigned long long y3 = dup2(xi.w);
        fma2(acc[0][0], q0.x, y0); fma2(acc[1][0], q0.x, y1);
        fma2(acc[2][0], q0.x, y2); fma2(acc[3][0], q0.x, y3);
        fma2(acc[0][1], q0.y, y0); fma2(acc[1][1], q0.y, y1);
        fma2(acc[2][1], q0.y, y2); fma2(acc[3][1], q0.y, y3);
        fma2(acc[0][2], q1.x, y0); fma2(acc[1][2], q1.x, y1);
        fma2(acc[2][2], q1.x, y2); fma2(acc[3][2], q1.x, y3);
        fma2(acc[0][3], q1.y, y0); fma2(acc[1][3], q1.y, y1);
        fma2(acc[2][3], q1.y, y2); fma2(acc[3][3], q1.y, y3);
        fma2(acc[0][4], q2.x, y0); fma2(acc[1][4], q2.x, y1);
        fma2(acc[2][4], q2.x, y2); fma2(acc[3][4], q2.x, y3);
        fma2(acc[0][5], q2.y, y0); fma2(acc[1][5], q2.y, y1);
        fma2(acc[2][5], q2.y, y2); fma2(acc[3][5], q2.y, y3);
        fma2(acc[0][6], q3.x, y0); fma2(acc[1][6], q3.x, y1);
        fma2(acc[2][6], q3.x, y2); fma2(acc[3][6], q3.x, y3);
    }

    // add a1 * w1 into basis smem
#pragma unroll
    for (int s = 0; s < NBSUB; s++) {
        float* bs = basS + ((g * NBSUB + s) * 64 + c) * 16;
#pragma unroll
        for (int k = 0; k < 7; k++) {
            float2 v = unpk2(acc[s][k]);
            int m0 = 2 * k, m1 = 2 * k + 1;
            bs[m0] += v.x * w1v[s][LSEL[m0]];
            if (m1 < 13) bs[m1] += v.y * w1v[s][LSEL[m1]];
        }
    }
    __syncthreads();

    // ---- reuse xS region for Wlin cache: wlS[l*4096 + cc*64 + o] ----
    float* wlS = S;
    {
        const float4* a0p = (const float4*)Wl0;
        const float4* a1p = (const float4*)Wl1;
        const float4* a2p = (const float4*)Wl2;
        float4* w4 = (float4*)wlS;
        for (int k = tid; k < 1024; k += NT) {
            w4[k]        = a0p[k];
            w4[1024 + k] = a1p[k];
            w4[2048 + k] = a2p[k];
        }
    }
    __syncthreads();

    // ---- self-interaction: r[s][m] = sum_cc basis[b_s][cc][m] * Wlin_l[cc][c] ----
    float r[NBSUB][13];
#pragma unroll
    for (int s = 0; s < NBSUB; s++)
#pragma unroll
        for (int m = 0; m < 13; m++) r[s][m] = 0.0f;

#pragma unroll 2
    for (int cc = 0; cc < 64; cc++) {
        float wv0 = wlS[cc * 64 + c];
        float wv1 = wlS[4096 + cc * 64 + c];
        float wv2 = wlS[8192 + cc * 64 + c];
#pragma unroll
        for (int s = 0; s < NBSUB; s++) {
            const float* br = basS + ((g * NBSUB + s) * 64 + cc) * 16;
            float4 b0 = *(const float4*)(br);
            float4 b1 = *(const float4*)(br + 4);
            float4 b2 = *(const float4*)(br + 8);
            float b12 = br[12];
            r[s][0]  += b0.x * wv0;
            r[s][1]  += b0.y * wv1;
            r[s][2]  += b0.z * wv1;
            r[s][3]  += b0.w * wv1;
            r[s][4]  += b1.x * wv2;
            r[s][5]  += b1.y * wv2;
            r[s][6]  += b1.z * wv2;
            r[s][7]  += b1.w * wv2;
            r[s][8]  += b2.x * wv2;
            r[s][9]  += b2.y * wv2;
            r[s][10] += b2.z * wv2;
            r[s][11] += b2.w * wv2;
            r[s][12] += b12  * wv2;
        }
    }

    // ---- outputs: concat [out0 (B,C)] [out1 (B,C,3)] [out2 (B,C,9)] ----
    float* o0 = out;
    float* o1 = out + (size_t)B * 64;
    float* o2 = out + (size_t)B * 64 * 4;
#pragma unroll
    for (int s = 0; s < NBSUB; s++) {
        int bb = bg + s;
        if (bb >= B) break;
        const int bo = bb * 64 + c;
        o0[bo] = r[s][0] + __ldg(&sc0[bo]);
#pragma unroll
        for (int k = 0; k < 3; k++)
            o1[bo * 3 + k] = r[s][1 + k] + __ldg(&sc1[bo * 3 + k]);
#pragma unroll
        for (int k = 0; k < 9; k++)
            o2[bo * 9 + k] = r[s][4 + k] + __ldg(&sc2[bo * 9 + k]);
    }
}

extern "C" void kernel_launch(void* const* d_in, const int* in_sizes, int n_in,
                              void* d_out, int out_size) {
    const float* f0    = (const float*)d_in[0];
    const float* f1    = (const float*)d_in[1];
    const float* f2    = (const float*)d_in[2];
    const float* f3    = (const float*)d_in[3];
    const float* attrs = (const float*)d_in[4];
    const float* U2_0  = (const float*)d_in[5];
    const float* U1_0  = (const float*)d_in[6];
    const float* W1_0  = (const float*)d_in[7];
    const float* W2_0  = (const float*)d_in[8];
    const float* Wl0   = (const float*)d_in[9];
    const float* sc0   = (const float*)d_in[10];
    const float* U2_1  = (const float*)d_in[11];
    const float* U1_1  = (const float*)d_in[12];
    const float* W1_1  = (const float*)d_in[13];
    const float* W2_1  = (const float*)d_in[14];
    const float* Wl1   = (const float*)d_in[15];
    const float* sc1   = (const float*)d_in[16];
    const float* U2_2  = (const float*)d_in[17];
    const float* U1_2  = (const float*)d_in[18];
    const float* W1_2  = (const float*)d_in[19];
    const float* W2_2  = (const float*)d_in[20];
    const float* Wl2   = (const float*)d_in[21];
    const float* sc2   = (const float*)d_in[22];

    const int B = in_sizes[0] / 64;

    cudaFuncSetAttribute(main_kernel,
                         cudaFuncAttributeMaxDynamicSharedMemorySize, SMEM_BYTES);

    prep_kernel<<<(NROWS + 255) / 256, 256>>>(U2_0, U1_0, U2_1, U1_1, U2_2, U1_2);

    const int grid = (B + NB - 1) / NB;
    main_kernel<<<grid, NT, SMEM_BYTES>>>(f0, f1, f2, f3, attrs,
                                          W1_0, W2_0, Wl0, sc0,
                                          W1_1, W2_1, Wl1, sc1,
                                          W1_2, W2_2, Wl2, sc2,
                                          (float*)d_out, B);
}